// round 6
// baseline (speedup 1.0000x reference)
#include <cuda_runtime.h>
#include <math.h>

#define HID 1024
#define LEN 40
#define VOC 50257
#define NPART 6283   // ceil(VOC/8)

// ---- scratch (no allocations allowed) ----
__device__ float g_concat[3 * HID];   // [embedded ; attn_applied]
__device__ float g_x[HID];            // relu(comb) output
__device__ float g_hl0[HID];          // layer-0 hidden out
__device__ float g_hl1[HID];          // layer-1 hidden out
__device__ float g_pm[NPART];         // per-block logit max
__device__ float g_ps[NPART];         // per-block expsum
__device__ float g_lse[1];

__device__ __forceinline__ float warp_reduce(float s) {
#pragma unroll
    for (int o = 16; o; o >>= 1) s += __shfl_down_sync(0xFFFFFFFFu, s, o);
    return s;
}

__device__ __forceinline__ float dot4(float4 a, float4 b) {
    return a.x * b.x + a.y * b.y + a.z * b.z + a.w * b.w;
}

// Four consecutive streaming LDG.128 with immediate offsets (stride 512 B =
// 32 float4, i.e. the per-lane stride when a warp covers a row). One asm
// volatile block => the 4 loads issue back-to-back in SASS; results must be
// register-resident. Two calls back-to-back give MLP=8 guaranteed.
__device__ __forceinline__ void ldg4x4(const float4* p,
                                       float4& a, float4& b, float4& c, float4& d) {
    asm volatile(
        "ld.global.cs.v4.f32 {%0,%1,%2,%3}, [%16];\n\t"
        "ld.global.cs.v4.f32 {%4,%5,%6,%7}, [%16+512];\n\t"
        "ld.global.cs.v4.f32 {%8,%9,%10,%11}, [%16+1024];\n\t"
        "ld.global.cs.v4.f32 {%12,%13,%14,%15}, [%16+1536];"
        : "=f"(a.x), "=f"(a.y), "=f"(a.z), "=f"(a.w),
          "=f"(b.x), "=f"(b.y), "=f"(b.z), "=f"(b.w),
          "=f"(c.x), "=f"(c.y), "=f"(c.z), "=f"(c.w),
          "=f"(d.x), "=f"(d.y), "=f"(d.z), "=f"(d.w)
        : "l"(p));
}

// ---------------------------------------------------------------------------
// K1: embedding gather + attention logits + softmax + context (one block)
// ---------------------------------------------------------------------------
__global__ void __launch_bounds__(512)
k_attn(const int* __restrict__ tok,
       const float* __restrict__ h0,
       const float* __restrict__ emb,
       const float* __restrict__ attn_w,
       const float* __restrict__ attn_b,
       const float* __restrict__ enc,
       float* __restrict__ out_attnw) {
    __shared__ float s_ain[3 * HID];
    __shared__ float s_log[LEN];
    __shared__ float s_w[LEN];
    int t = threadIdx.x;            // 512 threads
    int token = tok[0];
    for (int i = t; i < HID; i += 512) {
        s_ain[i]           = emb[(size_t)token * HID + i];
        s_ain[HID + i]     = h0[i];
        s_ain[2 * HID + i] = h0[HID + i];
    }
    __syncthreads();

    int warp = t >> 5, lane = t & 31;   // 16 warps
    for (int l = warp; l < LEN; l += 16) {
        const float4* w = (const float4*)(attn_w + (size_t)l * 3 * HID);
        const float4* a = (const float4*)s_ain;
        float s = 0.f;
#pragma unroll
        for (int c = 0; c < 3; c++) {   // 3 x (8 batched loads)
            float4 w0, w1, w2, w3, w4, w5, w6, w7;
            const float4* base = w + lane + 256 * c;
            ldg4x4(base,       w0, w1, w2, w3);
            ldg4x4(base + 128, w4, w5, w6, w7);
            int i0 = lane + 256 * c;
            s += dot4(a[i0],       w0) + dot4(a[i0 + 32],  w1)
               + dot4(a[i0 + 64],  w2) + dot4(a[i0 + 96],  w3)
               + dot4(a[i0 + 128], w4) + dot4(a[i0 + 160], w5)
               + dot4(a[i0 + 192], w6) + dot4(a[i0 + 224], w7);
        }
        s = warp_reduce(s);
        if (lane == 0) s_log[l] = s + attn_b[l];
    }
    __syncthreads();

    if (t == 0) {
        float m = s_log[0];
        for (int l = 1; l < LEN; l++) m = fmaxf(m, s_log[l]);
        float sum = 0.f;
        for (int l = 0; l < LEN; l++) { float e = expf(s_log[l] - m); s_w[l] = e; sum += e; }
        float inv = 1.f / sum;
        for (int l = 0; l < LEN; l++) { s_w[l] *= inv; out_attnw[l] = s_w[l]; }
    }
    __syncthreads();

    // attn_applied[j] = sum_l w[l] * enc[l, j], j in [0, 2H)
    for (int j = t; j < 2 * HID; j += 512) {
        float s = 0.f;
#pragma unroll
        for (int l = 0; l < LEN; l++) s += s_w[l] * enc[l * 2 * HID + j];
        g_concat[HID + j] = s;
    }
    for (int i = t; i < HID; i += 512) g_concat[i] = s_ain[i];   // embedded part
}

// ---------------------------------------------------------------------------
// K2: x = relu([emb;attn] @ comb_w.T + comb_b) — one warp per row, batched
// ---------------------------------------------------------------------------
__global__ void __launch_bounds__(256, 2)
k_comb(const float* __restrict__ comb_w,
       const float* __restrict__ comb_b) {
    int t = threadIdx.x;
    int wid = t >> 5, lane = t & 31;
    int row = blockIdx.x * 8 + wid;      // 128 blocks x 8 warps = 1024 rows
    const float4* w = (const float4*)(comb_w + (size_t)row * 3 * HID);
    const float4* v = (const float4*)g_concat;
    float s = 0.f;
#pragma unroll
    for (int c = 0; c < 3; c++) {
        float4 w0, w1, w2, w3, w4, w5, w6, w7;
        const float4* base = w + lane + 256 * c;
        ldg4x4(base,       w0, w1, w2, w3);
        ldg4x4(base + 128, w4, w5, w6, w7);
        int i0 = lane + 256 * c;
        s += dot4(v[i0],       w0) + dot4(v[i0 + 32],  w1)
           + dot4(v[i0 + 64],  w2) + dot4(v[i0 + 96],  w3)
           + dot4(v[i0 + 128], w4) + dot4(v[i0 + 160], w5)
           + dot4(v[i0 + 192], w6) + dot4(v[i0 + 224], w7);
    }
    s = warp_reduce(s);
    if (lane == 0) g_x[row] = fmaxf(s + comb_b[row], 0.f);
}

// ---------------------------------------------------------------------------
// K3: fused LSTM cell. Warp per (unit,gate): 512 blocks x 256 thr = 4096 warps.
// Block covers 2 units (warps 0-3: unit0 gates i,f,g,o; warps 4-7: unit1).
// ---------------------------------------------------------------------------
__global__ void __launch_bounds__(256, 2)
k_lstm(int layer,
       const float* __restrict__ hprev,
       const float* __restrict__ cprev,
       const float* __restrict__ w_ih,
       const float* __restrict__ w_hh,
       const float* __restrict__ b_ih,
       const float* __restrict__ b_hh,
       float* __restrict__ h_out,
       float* __restrict__ c_out) {
    __shared__ float s_g[8];
    int t = threadIdx.x;
    int wid = t >> 5, lane = t & 31;
    int uu = wid >> 2;                    // 0..1 unit within block
    int gate = wid & 3;                   // 0..3 (i,f,g,o)
    int u = blockIdx.x * 2 + uu;          // hidden unit
    int row = gate * HID + u;             // weight row

    const float4* wi = (const float4*)(w_ih + (size_t)row * HID);
    const float4* wh = (const float4*)(w_hh + (size_t)row * HID);
    const float4* x4 = (const float4*)(layer ? g_hl0 : g_x);
    const float4* h4 = (const float4*)hprev;

    float4 w0, w1, w2, w3, w4, w5, w6, w7;
    float sA = 0.f, sB = 0.f;
    // w_ih row: 8 loads in flight
    ldg4x4(wi + lane,       w0, w1, w2, w3);
    ldg4x4(wi + lane + 128, w4, w5, w6, w7);
    sA += dot4(x4[lane],       w0) + dot4(x4[lane + 32],  w1)
        + dot4(x4[lane + 64],  w2) + dot4(x4[lane + 96],  w3);
    sB += dot4(x4[lane + 128], w4) + dot4(x4[lane + 160], w5)
        + dot4(x4[lane + 192], w6) + dot4(x4[lane + 224], w7);
    // w_hh row: 8 loads in flight
    ldg4x4(wh + lane,       w0, w1, w2, w3);
    ldg4x4(wh + lane + 128, w4, w5, w6, w7);
    sA += dot4(h4[lane],       w0) + dot4(h4[lane + 32],  w1)
        + dot4(h4[lane + 64],  w2) + dot4(h4[lane + 96],  w3);
    sB += dot4(h4[lane + 128], w4) + dot4(h4[lane + 160], w5)
        + dot4(h4[lane + 192], w6) + dot4(h4[lane + 224], w7);

    float s = warp_reduce(sA + sB);
    if (lane == 0) s_g[wid] = s + b_ih[row] + b_hh[row];
    __syncthreads();

    if (t < 2) {
        int u2 = blockIdx.x * 2 + t;
        int b = t * 4;
        float gi = s_g[b + 0], gf = s_g[b + 1], gg = s_g[b + 2], go = s_g[b + 3];
        float si = 1.f / (1.f + expf(-gi));
        float sf = 1.f / (1.f + expf(-gf));
        float so = 1.f / (1.f + expf(-go));
        float c2 = sf * cprev[u2] + si * tanhf(gg);
        float h2 = so * tanhf(c2);
        c_out[u2] = c2;
        h_out[u2] = h2;
        if (layer) g_hl1[u2] = h2; else g_hl0[u2] = h2;
    }
}

// ---------------------------------------------------------------------------
// K5: logits = h_l1 @ out_w.T + out_b (warp per row) + per-block lse partials
// ---------------------------------------------------------------------------
__global__ void __launch_bounds__(256, 2)
k_logits(const float* __restrict__ out_w,
         const float* __restrict__ out_b,
         float* __restrict__ logits) {
    __shared__ float s_l[8];
    int t = threadIdx.x;
    int wid = t >> 5, lane = t & 31;
    int r = blockIdx.x * 8 + wid;

    if (r < VOC) {
        const float4* w = (const float4*)(out_w + (size_t)r * HID);
        const float4* h4 = (const float4*)g_hl1;
        float4 w0, w1, w2, w3, w4, w5, w6, w7;
        ldg4x4(w + lane,       w0, w1, w2, w3);
        ldg4x4(w + lane + 128, w4, w5, w6, w7);
        float sA = dot4(h4[lane],       w0) + dot4(h4[lane + 32],  w1)
                 + dot4(h4[lane + 64],  w2) + dot4(h4[lane + 96],  w3);
        float sB = dot4(h4[lane + 128], w4) + dot4(h4[lane + 160], w5)
                 + dot4(h4[lane + 192], w6) + dot4(h4[lane + 224], w7);
        float s = warp_reduce(sA + sB);
        if (lane == 0) {
            float lg = s + out_b[r];
            logits[r] = lg;
            s_l[wid] = lg;
        }
    } else if (lane == 0) {
        s_l[wid] = -INFINITY;
    }
    __syncthreads();

    if (t == 0) {
        float m = s_l[0];
#pragma unroll
        for (int k = 1; k < 8; k++) m = fmaxf(m, s_l[k]);
        float sum = 0.f;
#pragma unroll
        for (int k = 0; k < 8; k++) sum += expf(s_l[k] - m);
        g_pm[blockIdx.x] = m;
        g_ps[blockIdx.x] = sum;
    }
}

// ---------------------------------------------------------------------------
// K6: combine per-block partials into log-sum-exp (single block)
// ---------------------------------------------------------------------------
__global__ void __launch_bounds__(1024, 1)
k_lse(void) {
    __shared__ float red[1024];
    int t = threadIdx.x;
    float m = -INFINITY;
    for (int i = t; i < NPART; i += 1024) m = fmaxf(m, g_pm[i]);
    red[t] = m;
    __syncthreads();
    for (int o = 512; o; o >>= 1) {
        if (t < o) red[t] = fmaxf(red[t], red[t + o]);
        __syncthreads();
    }
    m = red[0];
    __syncthreads();
    float s = 0.f;
    for (int i = t; i < NPART; i += 1024) s += g_ps[i] * expf(g_pm[i] - m);
    red[t] = s;
    __syncthreads();
    for (int o = 512; o; o >>= 1) {
        if (t < o) red[t] += red[t + o];
        __syncthreads();
    }
    if (t == 0) g_lse[0] = m + logf(red[0]);
}

// K7: normalize in place
__global__ void __launch_bounds__(256)
k_sub(float* __restrict__ logits) {
    int i = blockIdx.x * blockDim.x + threadIdx.x;
    float lse = g_lse[0];
    if (i < VOC) logits[i] -= lse;
}

// ---------------------------------------------------------------------------
// Output layout: [log_probs(V) | h_new(2*H) | c_new(2*H) | attn_weights(L)]
// ---------------------------------------------------------------------------
extern "C" void kernel_launch(void* const* d_in, const int* in_sizes, int n_in,
                              void* d_out, int out_size) {
    const int*   tok    = (const int*)  d_in[0];
    const float* h0     = (const float*)d_in[1];   // [2,1,H]
    const float* c0     = (const float*)d_in[2];   // [2,1,H]
    const float* enc    = (const float*)d_in[3];   // [L, 2H]
    const float* emb    = (const float*)d_in[4];   // [V, H]
    const float* attn_w = (const float*)d_in[5];   // [L, 3H]
    const float* attn_b = (const float*)d_in[6];
    const float* comb_w = (const float*)d_in[7];   // [H, 3H]
    const float* comb_b = (const float*)d_in[8];
    const float* w_ih0  = (const float*)d_in[9];
    const float* w_hh0  = (const float*)d_in[10];
    const float* b_ih0  = (const float*)d_in[11];
    const float* b_hh0  = (const float*)d_in[12];
    const float* w_ih1  = (const float*)d_in[13];
    const float* w_hh1  = (const float*)d_in[14];
    const float* b_ih1  = (const float*)d_in[15];
    const float* b_hh1  = (const float*)d_in[16];
    const float* out_w  = (const float*)d_in[17];  // [V, H]
    const float* out_b  = (const float*)d_in[18];

    float* out      = (float*)d_out;
    float* o_logp   = out;                       // V
    float* o_h      = out + VOC;                 // 2H
    float* o_c      = out + VOC + 2 * HID;       // 2H
    float* o_attn   = out + VOC + 4 * HID;       // L

    k_attn<<<1, 512>>>(tok, h0, emb, attn_w, attn_b, enc, o_attn);
    k_comb<<<128, 256>>>(comb_w, comb_b);
    k_lstm<<<512, 256>>>(0, h0,       c0,       w_ih0, w_hh0, b_ih0, b_hh0,
                         o_h,       o_c);
    k_lstm<<<512, 256>>>(1, h0 + HID, c0 + HID, w_ih1, w_hh1, b_ih1, b_hh1,
                         o_h + HID, o_c + HID);
    k_logits<<<NPART, 256>>>(out_w, out_b, o_logp);
    k_lse<<<1, 1024>>>();
    k_sub<<<(VOC + 255) / 256, 256>>>(o_logp);
}